// round 1
// baseline (speedup 1.0000x reference)
#include <cuda_runtime.h>
#include <math.h>

#define BSZ     64
#define NF      16
#define NFILT   32          // 2*NF
#define KTAP    8
#define LSEQ    16384
#define THRV    0.25f
#define BETA    15.0f
#define TCH     512         // chunk length
#define WUP     96          // warm-up steps (alpha^96 ~ 1e-14, sub-ulp)
#define NCHUNK  (LSEQ / TCH)

// one warp per (b, chunk); lane = filter index 0..31
__global__ __launch_bounds__(64, 16)
void snn_scan_kernel(const float* __restrict__ x,
                     const float* __restrict__ wa,
                     const float* __restrict__ wb,
                     const float* __restrict__ ta,
                     const float* __restrict__ tb,
                     float* __restrict__ out)
{
    const int warp_global = (blockIdx.x * blockDim.x + threadIdx.x) >> 5;
    const int lane = threadIdx.x & 31;
    if (warp_global >= BSZ * NCHUNK) return;

    const int b     = warp_global / NCHUNK;
    const int chunk = warp_global % NCHUNK;
    const int f     = lane;
    const int ch    = f >> 4;            // 0: stream a, 1: stream b

    // ---- per-filter constants ----
    const float* wsrc = (ch == 0) ? (wa + f * KTAP) : (wb + (f - NF) * KTAP);
    float w[KTAP];
    float ss = 0.f;
    #pragma unroll
    for (int k = 0; k < KTAP; k++) { w[k] = wsrc[k]; ss = __fmaf_rn(w[k], w[k], ss); }
    const float inv = 1.0f / fmaxf(sqrtf(ss), 1e-8f);
    #pragma unroll
    for (int k = 0; k < KTAP; k++) w[k] = __fmul_rn(w[k], inv);

    const float raw   = (ch == 0) ? ta[f] : tb[f - NF];
    const float sp    = fmaxf(raw, 0.f) + log1pf(expf(-fabsf(raw)));   // softplus
    const float tau   = sp + 1e-4f;
    const float alpha = expf(-1.0f / tau);
    const float oma   = 1.0f - alpha;

    const float* xb = x + (size_t)(b * 2 + ch) * LSEQ;

    const int t0   = chunk * TCH;
    const int wlen = (chunk == 0) ? 0 : WUP;
    const int ts   = t0 - wlen;

    // ---- conv history window: hist[i] = x[tcur-8+i] ----
    float hist[8];
    if (chunk == 0) {
        #pragma unroll
        for (int k = 0; k < 8; k++) hist[k] = 0.f;   // causal left pad
    } else {
        const float4 h0 = *(const float4*)(xb + ts - 8);
        const float4 h1 = *(const float4*)(xb + ts - 4);
        hist[0]=h0.x; hist[1]=h0.y; hist[2]=h0.z; hist[3]=h0.w;
        hist[4]=h1.x; hist[5]=h1.y; hist[6]=h1.z; hist[7]=h1.w;
    }

    float v = 0.f;

    // ---- phase 1: warm-up (no outputs), contraction kills v(0) error ----
    for (int g = 0; g < wlen; g += 4) {
        const float4 c4 = *(const float4*)(xb + ts + g);
        float c[12];
        #pragma unroll
        for (int k = 0; k < 8; k++) c[k] = hist[k];
        c[8]=c4.x; c[9]=c4.y; c[10]=c4.z; c[11]=c4.w;
        #pragma unroll
        for (int j = 0; j < 4; j++) {
            float I = 0.f;
            #pragma unroll
            for (int k = 0; k < 8; k++) I = __fmaf_rn(w[k], c[j + 1 + k], I);
            const float vp = __fmaf_rn(alpha, v, __fmul_rn(oma, I));
            v = (vp >= THRV) ? 0.f : vp;
        }
        #pragma unroll
        for (int k = 0; k < 8; k++) hist[k] = c[k + 4];
    }

    // ---- output pointers ----
    const size_t plane = (size_t)BSZ * NFILT * LSEQ;
    const size_t base  = (size_t)(b * NFILT + f) * LSEQ + t0;
    float* __restrict__ vout = out + base;
    float* __restrict__ zout = out + plane + base;
    float* __restrict__ souT = out + 2 * plane + base;
    float* __restrict__ lout = out + 3 * plane + (size_t)b * LSEQ + t0;

    // ---- phase 2: main scan with outputs ----
    for (int g = 0; g < TCH; g += 4) {
        const float4 c4 = *(const float4*)(xb + t0 + g);
        float c[12];
        #pragma unroll
        for (int k = 0; k < 8; k++) c[k] = hist[k];
        c[8]=c4.x; c[9]=c4.y; c[10]=c4.z; c[11]=c4.w;

        float4 v4, z4, s4, l4;
        float* v4p = &v4.x; float* z4p = &z4.x; float* s4p = &s4.x; float* l4p = &l4.x;

        #pragma unroll
        for (int j = 0; j < 4; j++) {
            float I = 0.f;
            #pragma unroll
            for (int k = 0; k < 8; k++) I = __fmaf_rn(w[k], c[j + 1 + k], I);
            const float vp = __fmaf_rn(alpha, v, __fmul_rn(oma, I));
            const bool  spike = (vp >= THRV);
            const float z = __fmul_rn(BETA, __fadd_rn(vp, -THRV));   // matches ref op order
            v4p[j] = vp;                    // v history = pre-reset potential
            z4p[j] = z;
            s4p[j] = spike ? 1.0f : 0.0f;
            v      = spike ? 0.0f : vp;

            // warp max over 32 filters via monotone uint key + REDUX
            unsigned bits = __float_as_uint(z);
            unsigned key  = ((int)bits < 0) ? ~bits : (bits | 0x80000000u);
            unsigned kmax = __reduce_max_sync(0xffffffffu, key);
            unsigned rb   = (kmax & 0x80000000u) ? (kmax ^ 0x80000000u) : ~kmax;
            l4p[j] = __uint_as_float(rb);
        }

        *(float4*)(vout + g) = v4;
        *(float4*)(zout + g) = z4;
        *(float4*)(souT + g) = s4;
        if (lane == 0) *(float4*)(lout + g) = l4;

        #pragma unroll
        for (int k = 0; k < 8; k++) hist[k] = c[k + 4];
    }
}

extern "C" void kernel_launch(void* const* d_in, const int* in_sizes, int n_in,
                              void* d_out, int out_size)
{
    const float* x  = (const float*)d_in[0];
    const float* wa = (const float*)d_in[1];
    const float* wb = (const float*)d_in[2];
    const float* ta = (const float*)d_in[3];
    const float* tb = (const float*)d_in[4];
    float* out = (float*)d_out;

    // 2048 warps total: one per (b, chunk); 2 warps/block -> 1024 blocks
    const int total_warps = BSZ * NCHUNK;
    const int threads = 64;
    const int blocks  = (total_warps * 32) / threads;
    snn_scan_kernel<<<blocks, threads>>>(x, wa, wb, ta, tb, out);
}